// round 2
// baseline (speedup 1.0000x reference)
#include <cuda_runtime.h>
#include <math.h>

#define T 8
#define NN 4096
#define F 256
#define FF (F*F)          // 65536
#define NF (NN*F)         // 1048576

// ---------------- scratch (static device memory; no allocations) -----------
__device__ float g_zt[T*FF];        // zt per timestep (current layer)
__device__ float g_P[3*T*FF];       // Wg @ zt[t], gate-major [gate][t]
__device__ float g_Q[FF];           // evolving Q
__device__ float g_Qseq[T*FF];      // layer-0 Qn sequence
__device__ float g_U2[2*FF];        // packed [Uz;Ur]
__device__ float g_AzAr[2*FF];      // Uz@Q ; Ur@Q
__device__ float g_upd[FF];
__device__ float g_RQ[FF];
__device__ float g_Ah[FF];
__device__ float g_Y[T*NF];         // X[t] @ Qseq[t]
__device__ float g_h1top[T*FF];     // first 256 rows of h1[t]
__device__ float g_h1full[NF];      // full h1[7]
__device__ float g_Z[NF];           // h1[7] @ Q1

// ---------------- generic fp32 GEMM: C[64x64 tile] = A@B (+relu) -----------
// A row-major [M,K] lda ; B row-major [K,N] ldb ; C row-major ldc.
// grid = (N/64, M/64, batch); per-batch offsets sA,sB,sC (elements).
__global__ void __launch_bounds__(256) gemm64(
    const float* __restrict__ Ab, const float* __restrict__ Bb,
    float* __restrict__ Cb,
    int K, int lda, int ldb, int ldc,
    long sA, long sB, long sC, int act)
{
    const float* A = Ab + (long)blockIdx.z * sA;
    const float* B = Bb + (long)blockIdx.z * sB;
    float*       C = Cb + (long)blockIdx.z * sC;

    const int tid = threadIdx.x;
    const int tx = tid & 15, ty = tid >> 4;
    const int bm = blockIdx.y << 6, bn = blockIdx.x << 6;

    __shared__ float As[64][17];
    __shared__ float Bs[16][64];

    const int arow = tid >> 2, akc = (tid & 3) << 2;   // A tile: 64 rows x 16 k
    const int brow = tid >> 4, bcol = (tid & 15) << 2; // B tile: 16 k x 64 cols

    float acc[4][4];
#pragma unroll
    for (int i = 0; i < 4; i++)
#pragma unroll
        for (int j = 0; j < 4; j++) acc[i][j] = 0.f;

    const int ty4 = ty << 2, tx4 = tx << 2;

    for (int k0 = 0; k0 < K; k0 += 16) {
        float4 av = *reinterpret_cast<const float4*>(&A[(long)(bm + arow) * lda + k0 + akc]);
        float4 bv = *reinterpret_cast<const float4*>(&B[(long)(k0 + brow) * ldb + bn + bcol]);
        As[arow][akc + 0] = av.x; As[arow][akc + 1] = av.y;
        As[arow][akc + 2] = av.z; As[arow][akc + 3] = av.w;
        *reinterpret_cast<float4*>(&Bs[brow][bcol]) = bv;
        __syncthreads();
#pragma unroll
        for (int k = 0; k < 16; k++) {
            float a0 = As[ty4 + 0][k], a1 = As[ty4 + 1][k];
            float a2 = As[ty4 + 2][k], a3 = As[ty4 + 3][k];
            float4 b = *reinterpret_cast<const float4*>(&Bs[k][tx4]);
            acc[0][0] += a0 * b.x; acc[0][1] += a0 * b.y; acc[0][2] += a0 * b.z; acc[0][3] += a0 * b.w;
            acc[1][0] += a1 * b.x; acc[1][1] += a1 * b.y; acc[1][2] += a1 * b.z; acc[1][3] += a1 * b.w;
            acc[2][0] += a2 * b.x; acc[2][1] += a2 * b.y; acc[2][2] += a2 * b.z; acc[2][3] += a2 * b.w;
            acc[3][0] += a3 * b.x; acc[3][1] += a3 * b.y; acc[3][2] += a3 * b.z; acc[3][3] += a3 * b.w;
        }
        __syncthreads();
    }

#pragma unroll
    for (int i = 0; i < 4; i++) {
        float4 v = make_float4(acc[i][0], acc[i][1], acc[i][2], acc[i][3]);
        if (act) {
            v.x = fmaxf(v.x, 0.f); v.y = fmaxf(v.y, 0.f);
            v.z = fmaxf(v.z, 0.f); v.w = fmaxf(v.w, 0.f);
        }
        *reinterpret_cast<float4*>(&C[(long)(bm + ty4 + i) * ldc + bn + tx4]) = v;
    }
}

// ---------------- zt: zt[t][c*256+r] = embs_t[r][c] * tanh((embs_t[r]·s)/|s|)
__global__ void zt_kernel(const float* __restrict__ embs, long embStride, int ld,
                          const float* __restrict__ scorer, float* __restrict__ ztOut)
{
    const int t = blockIdx.x;
    const float* E = embs + (long)t * embStride;
    float* zt = ztOut + (long)t * FF;

    __shared__ float sc[F];
    __shared__ float th[F];
    __shared__ float red[256];

    const int tid = threadIdx.x;   // 256 threads
    float s = scorer[tid];
    sc[tid] = s;
    red[tid] = s * s;
    __syncthreads();
    for (int off = 128; off > 0; off >>= 1) {
        if (tid < off) red[tid] += red[tid + off];
        __syncthreads();
    }
    const float inv_sn = 1.0f / sqrtf(red[0]);

    float dot = 0.f;
    const float* row = E + (long)tid * ld;
#pragma unroll 8
    for (int c = 0; c < F; c++) dot += row[c] * sc[c];
    th[tid] = tanhf(dot * inv_sn);
    __syncthreads();

    for (int i = tid; i < FF; i += 256) {
        int r = i & 255, c = i >> 8;
        zt[i] = E[(long)r * ld + c] * th[r];
    }
}

__device__ __forceinline__ float sigf(float x) { return 1.0f / (1.0f + expf(-x)); }

// upd = sigmoid(Pz+Az+bz); RQ = sigmoid(Pr+Ar+br) * Q
__global__ void gru_ew1(const float* __restrict__ Pz, const float* __restrict__ Az,
                        const float* __restrict__ bz,
                        const float* __restrict__ Pr, const float* __restrict__ Ar,
                        const float* __restrict__ br,
                        const float* __restrict__ Q,
                        float* __restrict__ upd, float* __restrict__ RQ)
{
    int i = blockIdx.x * 256 + threadIdx.x;
    float u = sigf(Pz[i] + Az[i] + bz[i]);
    float r = sigf(Pr[i] + Ar[i] + br[i]);
    upd[i] = u;
    RQ[i] = r * Q[i];
}

// hcap = tanh(Ph+Ah+bh); Qn = (1-u)*Q + u*hcap
__global__ void gru_ew2(const float* __restrict__ Ph, const float* __restrict__ Ah,
                        const float* __restrict__ bh,
                        const float* __restrict__ upd, const float* __restrict__ Qin,
                        float* __restrict__ Qout, float* __restrict__ Qseq)
{
    int i = blockIdx.x * 256 + threadIdx.x;
    float h = tanhf(Ph[i] + Ah[i] + bh[i]);
    float u = upd[i];
    float q = (1.0f - u) * Qin[i] + u * h;
    Qout[i] = q;
    if (Qseq) Qseq[i] = q;
}

__global__ void copy2(const float* __restrict__ a, const float* __restrict__ b,
                      float* __restrict__ dst)
{
    int i = blockIdx.x * 256 + threadIdx.x;
    dst[i] = a[i];
    dst[FF + i] = b[i];
}

__global__ void copy1(const float* __restrict__ src, float* __restrict__ dst)
{
    int i = blockIdx.x * 256 + threadIdx.x;
    dst[i] = src[i];
}

// ---------------------------------------------------------------------------
extern "C" void kernel_launch(void* const* d_in, const int* in_sizes, int n_in,
                              void* d_out, int out_size)
{
    const float* Aadj = (const float*)d_in[0];  // [T,N,N]
    const float* X    = (const float*)d_in[1];  // [T,N,F]
    // d_in[2] = mask (unused)

    // per-layer params: 0 scorer,1 Wz,2 Uz,3 bz,4 Wr,5 Ur,6 br,7 Wh,8 Uh,9 bh,10 Q0
    auto LP = [&](int l, int idx) { return (const float*)d_in[3 + l * 11 + idx]; };

    float *zt, *P, *Q, *Qseq, *U2, *AzAr, *upd, *RQ, *Ah, *Y, *h1top, *h1full, *Z;
    cudaGetSymbolAddress((void**)&zt,     g_zt);
    cudaGetSymbolAddress((void**)&P,      g_P);
    cudaGetSymbolAddress((void**)&Q,      g_Q);
    cudaGetSymbolAddress((void**)&Qseq,   g_Qseq);
    cudaGetSymbolAddress((void**)&U2,     g_U2);
    cudaGetSymbolAddress((void**)&AzAr,   g_AzAr);
    cudaGetSymbolAddress((void**)&upd,    g_upd);
    cudaGetSymbolAddress((void**)&RQ,     g_RQ);
    cudaGetSymbolAddress((void**)&Ah,     g_Ah);
    cudaGetSymbolAddress((void**)&Y,      g_Y);
    cudaGetSymbolAddress((void**)&h1top,  g_h1top);
    cudaGetSymbolAddress((void**)&h1full, g_h1full);
    cudaGetSymbolAddress((void**)&Z,      g_Z);

    // =================== Layer 0 ===================
    // zt for all timesteps (depends only on X)
    zt_kernel<<<T, 256>>>(X, (long)NN * F, F, LP(0, 0), zt);

    // P[g][t] = Wg @ zt[t]  (batched over t per gate)
    {
        const int wIdx[3] = {1, 4, 7}; // Wz, Wr, Wh
        for (int g = 0; g < 3; g++)
            gemm64<<<dim3(4, 4, T), 256>>>(LP(0, wIdx[g]), zt, P + (long)g * T * FF,
                                           F, F, F, F, 0, FF, FF, 0);
    }
    copy2<<<256, 256>>>(LP(0, 2), LP(0, 5), U2); // pack Uz,Ur

    for (int t = 0; t < T; t++) {
        const float* Qp = (t == 0) ? LP(0, 10) : Q;
        gemm64<<<dim3(4, 4, 2), 256>>>(U2, Qp, AzAr, F, F, F, F, FF, 0, FF, 0);
        gru_ew1<<<256, 256>>>(P + (long)t * FF, AzAr, LP(0, 3),
                              P + (long)(T + t) * FF, AzAr + FF, LP(0, 6),
                              Qp, upd, RQ);
        gemm64<<<dim3(4, 4, 1), 256>>>(LP(0, 8), RQ, Ah, F, F, F, F, 0, 0, 0, 0);
        gru_ew2<<<256, 256>>>(P + (long)(2 * T + t) * FF, Ah, LP(0, 9),
                              upd, Qp, Q, Qseq + (long)t * FF);
    }

    // Y[t] = X[t] @ Qseq[t]   (batched)
    gemm64<<<dim3(4, 64, T), 256>>>(X, Qseq, Y, F, F, F, F, (long)NF, FF, (long)NF, 0);

    // h1top[t] = relu(A[t][:256,:] @ Y[t]), t = 0..6 (batched)
    gemm64<<<dim3(4, 4, 7), 256>>>(Aadj, Y, h1top, NN, NN, F, F,
                                   (long)NN * NN, (long)NF, FF, 1);
    // h1full = relu(A[7] @ Y[7])
    gemm64<<<dim3(4, 64, 1), 256>>>(Aadj + 7L * NN * NN, Y + 7L * NF, h1full,
                                    NN, NN, F, F, 0, 0, 0, 1);
    // h1top[7] = first 256 rows of h1full (contiguous)
    copy1<<<256, 256>>>(h1full, h1top + 7L * FF);

    // =================== Layer 1 ===================
    zt_kernel<<<T, 256>>>(h1top, (long)FF, F, LP(1, 0), zt);
    {
        const int wIdx[3] = {1, 4, 7};
        for (int g = 0; g < 3; g++)
            gemm64<<<dim3(4, 4, T), 256>>>(LP(1, wIdx[g]), zt, P + (long)g * T * FF,
                                           F, F, F, F, 0, FF, FF, 0);
    }
    copy2<<<256, 256>>>(LP(1, 2), LP(1, 5), U2);

    for (int t = 0; t < T; t++) {
        const float* Qp = (t == 0) ? LP(1, 10) : Q;
        gemm64<<<dim3(4, 4, 2), 256>>>(U2, Qp, AzAr, F, F, F, F, FF, 0, FF, 0);
        gru_ew1<<<256, 256>>>(P + (long)t * FF, AzAr, LP(1, 3),
                              P + (long)(T + t) * FF, AzAr + FF, LP(1, 6),
                              Qp, upd, RQ);
        gemm64<<<dim3(4, 4, 1), 256>>>(LP(1, 8), RQ, Ah, F, F, F, F, 0, 0, 0, 0);
        gru_ew2<<<256, 256>>>(P + (long)(2 * T + t) * FF, Ah, LP(1, 9),
                              upd, Qp, Q, nullptr);
    }

    // out = relu(A[7] @ (h1full @ Q1))
    gemm64<<<dim3(4, 64, 1), 256>>>(h1full, Q, Z, F, F, F, F, 0, 0, 0, 0);
    gemm64<<<dim3(4, 64, 1), 256>>>(Aadj + 7L * NN * NN, Z, (float*)d_out,
                                    NN, NN, F, F, 0, 0, 0, 1);
}

// round 3
// speedup vs baseline: 1.4661x; 1.4661x over previous
#include <cuda_runtime.h>
#include <math.h>

typedef unsigned long long ull;

#define T 8
#define NN 4096
#define F 256
#define FF (F*F)          // 65536
#define NF (NN*F)         // 1048576
#define NSPLIT 4

// ---------------- scratch (static device memory; no allocations) -----------
__device__ float g_zt[T*FF];
__device__ float g_P[3*T*FF];       // [gate][t][FF]
__device__ float g_Q[FF];
__device__ float g_Qseq[T*FF];
__device__ float g_W3[3*FF];        // packed Wz,Wr,Wh
__device__ float g_upd[FF];
__device__ float g_RQ[FF];
__device__ float g_Y[T*NF];
__device__ float g_part[7*NSPLIT*FF];
__device__ float g_h1top[T*FF];
__device__ float g_h1full[NF];
__device__ float g_Z[NF];

// ---------------- f32x2 helpers --------------------------------------------
__device__ __forceinline__ ull pk2(float lo, float hi) {
    ull r; asm("mov.b64 %0, {%1, %2};" : "=l"(r) : "f"(lo), "f"(hi)); return r;
}
__device__ __forceinline__ float lo32(ull v){ return __uint_as_float((unsigned)v); }
__device__ __forceinline__ float hi32(ull v){ return __uint_as_float((unsigned)(v >> 32)); }
#define FMA2(acc, a, b) asm("fma.rn.f32x2 %0, %1, %2, %0;" : "+l"(acc) : "l"(a), "l"(b))

// ---------------- big GEMM: 128x64 tile, FFMA2, double-buffered -------------
// C = A@B (+relu). A row-major [M,K] lda, B row-major [K,N] ldb.
// grid (N/64, M/128, batch). batch mapping:
//  mode 0: A+=z*sA, B+=z*sB, C+=z*sC
//  mode 1: A+=(z>>3)*sA, B+=(z&7)*sB, C+=z*sC          (P = W[g] @ zt[t])
//  mode 2: t=z>>2,s=z&3: A+=t*sA + s*K (cols), B+=t*sB + s*K*ldb, C+=z*sC (split-K)
__global__ void __launch_bounds__(256, 2) gemm_big(
    const float* __restrict__ Ab, const float* __restrict__ Bb, float* __restrict__ Cb,
    int K, int lda, int ldb, int ldc,
    long sA, long sB, long sC, int act, int mode)
{
    const int z = blockIdx.z;
    const float* A; const float* B; float* C;
    if (mode == 0)      { A = Ab + z * sA; B = Bb + z * sB; C = Cb + z * sC; }
    else if (mode == 1) { A = Ab + (long)(z >> 3) * sA; B = Bb + (long)(z & 7) * sB; C = Cb + (long)z * sC; }
    else                { int t = z >> 2, s = z & 3;
                          A = Ab + (long)t * sA + (long)s * K;
                          B = Bb + (long)t * sB + (long)s * K * ldb;
                          C = Cb + (long)z * sC; }

    __shared__ float As[2][16][136];   // transposed A tile, conflict-free pad
    __shared__ float Bs[2][16][64];

    const int tid = threadIdx.x;
    const int tx = tid & 15, ty = tid >> 4;
    const long bm = (long)blockIdx.y << 7;
    const int  bn = blockIdx.x << 6;

    const int a_row = tid >> 2;          // 0..63 (and +64)
    const int a_kc  = (tid & 3) << 2;
    const int b_kr  = tid >> 4;
    const int b_kc  = (tid & 15) << 2;

    const float* Ap0 = A + (bm + a_row) * (long)lda + a_kc;
    const float* Ap1 = Ap0 + (long)64 * lda;
    const float* Bp  = B + (long)b_kr * ldb + bn + b_kc;

    {   // prologue: tile 0
        float4 va0 = *(const float4*)Ap0;
        float4 va1 = *(const float4*)Ap1;
        float4 vb  = *(const float4*)Bp;
        As[0][a_kc+0][a_row] = va0.x; As[0][a_kc+1][a_row] = va0.y;
        As[0][a_kc+2][a_row] = va0.z; As[0][a_kc+3][a_row] = va0.w;
        As[0][a_kc+0][a_row+64] = va1.x; As[0][a_kc+1][a_row+64] = va1.y;
        As[0][a_kc+2][a_row+64] = va1.z; As[0][a_kc+3][a_row+64] = va1.w;
        *(float4*)&Bs[0][b_kr][b_kc] = vb;
    }
    __syncthreads();

    ull acc[4][4];
#pragma unroll
    for (int p = 0; p < 4; p++)
#pragma unroll
        for (int j = 0; j < 4; j++) acc[p][j] = 0ULL;

    const int nIter = K >> 4;
    int buf = 0;
    for (int it = 0; it < nIter; ++it) {
        float4 na0, na1, nb;
        const bool more = (it + 1 < nIter);
        if (more) {
            na0 = *(const float4*)(Ap0 + (it + 1) * 16);
            na1 = *(const float4*)(Ap1 + (it + 1) * 16);
            nb  = *(const float4*)(Bp + (long)(it + 1) * 16 * ldb);
        }
#pragma unroll
        for (int k = 0; k < 16; ++k) {
            ull a0 = *(const ull*)&As[buf][k][(ty<<3) + 0];
            ull a1 = *(const ull*)&As[buf][k][(ty<<3) + 2];
            ull a2 = *(const ull*)&As[buf][k][(ty<<3) + 4];
            ull a3 = *(const ull*)&As[buf][k][(ty<<3) + 6];
            float4 bv = *(const float4*)&Bs[buf][k][tx<<2];
            ull b0 = pk2(bv.x, bv.x), b1 = pk2(bv.y, bv.y);
            ull b2 = pk2(bv.z, bv.z), b3 = pk2(bv.w, bv.w);
            FMA2(acc[0][0], a0, b0); FMA2(acc[0][1], a0, b1); FMA2(acc[0][2], a0, b2); FMA2(acc[0][3], a0, b3);
            FMA2(acc[1][0], a1, b0); FMA2(acc[1][1], a1, b1); FMA2(acc[1][2], a1, b2); FMA2(acc[1][3], a1, b3);
            FMA2(acc[2][0], a2, b0); FMA2(acc[2][1], a2, b1); FMA2(acc[2][2], a2, b2); FMA2(acc[2][3], a2, b3);
            FMA2(acc[3][0], a3, b0); FMA2(acc[3][1], a3, b1); FMA2(acc[3][2], a3, b2); FMA2(acc[3][3], a3, b3);
        }
        if (more) {
            const int nbuf = buf ^ 1;
            As[nbuf][a_kc+0][a_row] = na0.x; As[nbuf][a_kc+1][a_row] = na0.y;
            As[nbuf][a_kc+2][a_row] = na0.z; As[nbuf][a_kc+3][a_row] = na0.w;
            As[nbuf][a_kc+0][a_row+64] = na1.x; As[nbuf][a_kc+1][a_row+64] = na1.y;
            As[nbuf][a_kc+2][a_row+64] = na1.z; As[nbuf][a_kc+3][a_row+64] = na1.w;
            *(float4*)&Bs[nbuf][b_kr][b_kc] = nb;
        }
        __syncthreads();
        buf ^= 1;
    }

#pragma unroll
    for (int p = 0; p < 4; ++p) {
        float4 vlo = make_float4(lo32(acc[p][0]), lo32(acc[p][1]), lo32(acc[p][2]), lo32(acc[p][3]));
        float4 vhi = make_float4(hi32(acc[p][0]), hi32(acc[p][1]), hi32(acc[p][2]), hi32(acc[p][3]));
        if (act) {
            vlo.x = fmaxf(vlo.x, 0.f); vlo.y = fmaxf(vlo.y, 0.f);
            vlo.z = fmaxf(vlo.z, 0.f); vlo.w = fmaxf(vlo.w, 0.f);
            vhi.x = fmaxf(vhi.x, 0.f); vhi.y = fmaxf(vhi.y, 0.f);
            vhi.z = fmaxf(vhi.z, 0.f); vhi.w = fmaxf(vhi.w, 0.f);
        }
        long r = bm + (ty << 3) + (p << 1);
        *(float4*)&C[r * (long)ldc + bn + (tx << 2)]       = vlo;
        *(float4*)&C[(r + 1) * (long)ldc + bn + (tx << 2)] = vhi;
    }
}

// ---------------- GRU GEMM (64x64 tile) with fused gate epilogues -----------
// MODE 0 (grid (4,4,2)): z=0: upd = sig(Uz@Q + Pz + bz)
//                        z=1: RQ  = sig(Ur@Q + Pr + br) * Q
// MODE 1 (grid (4,4,1)): h = tanh(Uh@RQ + Ph + bh); Qn = (1-u)Q + u*h -> out0 (+out1)
template<int MODE>
__global__ void __launch_bounds__(256) gemm_gru(
    const float* __restrict__ Az_, const float* __restrict__ Ar_,
    const float* __restrict__ Bmat,
    const float* __restrict__ Pz, const float* __restrict__ Pr,
    const float* __restrict__ bz, const float* __restrict__ br,
    const float* __restrict__ Qin, const float* __restrict__ upd_in,
    float* __restrict__ out0, float* __restrict__ out1)
{
    const float* A; const float* P; const float* bb;
    if (MODE == 0 && blockIdx.z == 1) { A = Ar_; P = Pr; bb = br; }
    else                              { A = Az_; P = Pz; bb = bz; }

    __shared__ float As[2][16][72];
    __shared__ float Bs[2][16][64];

    const int tid = threadIdx.x;
    const int tx = tid & 15, ty = tid >> 4;
    const int bm = blockIdx.y << 6;
    const int bn = blockIdx.x << 6;

    const int a_row = tid >> 2;
    const int a_kc  = (tid & 3) << 2;
    const int b_kr  = tid >> 4;
    const int b_kc  = (tid & 15) << 2;

    const float* Ap = A + (bm + a_row) * F + a_kc;
    const float* Bp = Bmat + b_kr * F + bn + b_kc;

    {
        float4 va = *(const float4*)Ap;
        float4 vb = *(const float4*)Bp;
        As[0][a_kc+0][a_row] = va.x; As[0][a_kc+1][a_row] = va.y;
        As[0][a_kc+2][a_row] = va.z; As[0][a_kc+3][a_row] = va.w;
        *(float4*)&Bs[0][b_kr][b_kc] = vb;
    }
    __syncthreads();

    ull acc[2][4];
#pragma unroll
    for (int p = 0; p < 2; p++)
#pragma unroll
        for (int j = 0; j < 4; j++) acc[p][j] = 0ULL;

    int buf = 0;
    for (int it = 0; it < 16; ++it) {
        float4 na, nb;
        const bool more = (it < 15);
        if (more) {
            na = *(const float4*)(Ap + (it + 1) * 16);
            nb = *(const float4*)(Bp + (it + 1) * 16 * F);
        }
#pragma unroll
        for (int k = 0; k < 16; ++k) {
            ull a0 = *(const ull*)&As[buf][k][(ty<<2) + 0];
            ull a1 = *(const ull*)&As[buf][k][(ty<<2) + 2];
            float4 bv = *(const float4*)&Bs[buf][k][tx<<2];
            ull b0 = pk2(bv.x, bv.x), b1 = pk2(bv.y, bv.y);
            ull b2 = pk2(bv.z, bv.z), b3 = pk2(bv.w, bv.w);
            FMA2(acc[0][0], a0, b0); FMA2(acc[0][1], a0, b1); FMA2(acc[0][2], a0, b2); FMA2(acc[0][3], a0, b3);
            FMA2(acc[1][0], a1, b0); FMA2(acc[1][1], a1, b1); FMA2(acc[1][2], a1, b2); FMA2(acc[1][3], a1, b3);
        }
        if (more) {
            const int nbuf = buf ^ 1;
            As[nbuf][a_kc+0][a_row] = na.x; As[nbuf][a_kc+1][a_row] = na.y;
            As[nbuf][a_kc+2][a_row] = na.z; As[nbuf][a_kc+3][a_row] = na.w;
            *(float4*)&Bs[nbuf][b_kr][b_kc] = nb;
        }
        __syncthreads();
        buf ^= 1;
    }

#pragma unroll
    for (int p = 0; p < 2; ++p) {
#pragma unroll
        for (int e = 0; e < 2; ++e) {
            int row = bm + (ty << 2) + (p << 1) + e;
#pragma unroll
            for (int j = 0; j < 4; ++j) {
                int col = bn + (tx << 2) + j;
                long idx = (long)row * F + col;
                float a = e ? hi32(acc[p][j]) : lo32(acc[p][j]);
                float v = a + P[idx] + bb[idx];
                if (MODE == 0) {
                    float s = 1.0f / (1.0f + expf(-v));
                    if (blockIdx.z == 0) out0[idx] = s;
                    else                 out1[idx] = s * Qin[idx];
                } else {
                    float h = tanhf(v);
                    float u = upd_in[idx];
                    float q = (1.0f - u) * Qin[idx] + u * h;
                    out0[idx] = q;
                    if (out1) out1[idx] = q;
                }
            }
        }
    }
}

// ---------------- zt: zt[t][f*256+j] = embs_t[j][f] * tanh((embs_t[j]·s)/|s|)
__global__ void zt_kernel(const float* __restrict__ embs, long embStride, int ld,
                          const float* __restrict__ scorer, float* __restrict__ ztOut)
{
    const int t = blockIdx.x;
    const float* E = embs + (long)t * embStride;
    float* zt = ztOut + (long)t * FF;

    __shared__ float sc[F];
    __shared__ float th[F];
    __shared__ float red[256];

    const int tid = threadIdx.x;
    float s = scorer[tid];
    sc[tid] = s;
    red[tid] = s * s;
    __syncthreads();
    for (int off = 128; off > 0; off >>= 1) {
        if (tid < off) red[tid] += red[tid + off];
        __syncthreads();
    }
    const float inv_sn = 1.0f / sqrtf(red[0]);

    float dot = 0.f;
    const float* row = E + (long)tid * ld;
#pragma unroll 8
    for (int c = 0; c < F; c++) dot += row[c] * sc[c];
    th[tid] = tanhf(dot * inv_sn);
    __syncthreads();

    for (int i = tid; i < FF; i += 256) {
        int r = i & 255, c = i >> 8;
        zt[i] = E[(long)r * ld + c] * th[r];
    }
}

// ---------------- misc -------------------------------------------------------
__global__ void reduce_relu(const float* __restrict__ part, float* __restrict__ out)
{
    long i = (long)blockIdx.x * 256 + threadIdx.x;   // over 7*FF
    long t = i >> 16;
    long r = i & (FF - 1);
    const float* p = part + t * (long)(NSPLIT * FF) + r;
    float s = p[0] + p[FF] + p[2 * FF] + p[3 * FF];
    out[i] = fmaxf(s, 0.0f);
}

__global__ void pack3(const float* __restrict__ a, const float* __restrict__ b,
                      const float* __restrict__ c, float* __restrict__ dst)
{
    int i = blockIdx.x * 256 + threadIdx.x;
    dst[i] = a[i]; dst[FF + i] = b[i]; dst[2 * FF + i] = c[i];
}

__global__ void copy1(const float* __restrict__ src, float* __restrict__ dst)
{
    int i = blockIdx.x * 256 + threadIdx.x;
    dst[i] = src[i];
}

// ---------------------------------------------------------------------------
extern "C" void kernel_launch(void* const* d_in, const int* in_sizes, int n_in,
                              void* d_out, int out_size)
{
    const float* Aadj = (const float*)d_in[0];  // [T,N,N]
    const float* X    = (const float*)d_in[1];  // [T,N,F]
    auto LP = [&](int l, int idx) { return (const float*)d_in[3 + l * 11 + idx]; };

    float *zt, *P, *Q, *Qseq, *W3, *upd, *RQ, *Y, *part, *h1top, *h1full, *Z;
    cudaGetSymbolAddress((void**)&zt,     g_zt);
    cudaGetSymbolAddress((void**)&P,      g_P);
    cudaGetSymbolAddress((void**)&Q,      g_Q);
    cudaGetSymbolAddress((void**)&Qseq,   g_Qseq);
    cudaGetSymbolAddress((void**)&W3,     g_W3);
    cudaGetSymbolAddress((void**)&upd,    g_upd);
    cudaGetSymbolAddress((void**)&RQ,     g_RQ);
    cudaGetSymbolAddress((void**)&Y,      g_Y);
    cudaGetSymbolAddress((void**)&part,   g_part);
    cudaGetSymbolAddress((void**)&h1top,  g_h1top);
    cudaGetSymbolAddress((void**)&h1full, g_h1full);
    cudaGetSymbolAddress((void**)&Z,      g_Z);

    for (int l = 0; l < 2; ++l) {
        // zt for all timesteps
        if (l == 0) zt_kernel<<<T, 256>>>(X,     (long)NF, F, LP(0, 0), zt);
        else        zt_kernel<<<T, 256>>>(h1top, (long)FF, F, LP(1, 0), zt);

        // pack gate weights, then P[g][t] = W[g] @ zt[t] in ONE launch
        pack3<<<FF / 256, 256>>>(LP(l, 1), LP(l, 4), LP(l, 7), W3);
        gemm_big<<<dim3(4, 2, 24), 256>>>(W3, zt, P, F, F, F, F,
                                          (long)FF, (long)FF, (long)FF, 0, 1);

        // GRU chain: 2 fused launches per step
        for (int t = 0; t < T; ++t) {
            const float* Qp = (t == 0) ? LP(l, 10) : Q;
            gemm_gru<0><<<dim3(4, 4, 2), 256>>>(LP(l, 2), LP(l, 5), Qp,
                P + (long)t * FF, P + (long)(T + t) * FF, LP(l, 3), LP(l, 6),
                Qp, nullptr, upd, RQ);
            gemm_gru<1><<<dim3(4, 4, 1), 256>>>(LP(l, 8), nullptr, RQ,
                P + (long)(2 * T + t) * FF, nullptr, LP(l, 9), nullptr,
                Qp, upd, Q, (l == 0) ? Qseq + (long)t * FF : nullptr);
        }

        if (l == 0) {
            // Y[t] = X[t] @ Qseq[t]  (batched)
            gemm_big<<<dim3(4, 32, 8), 256>>>(X, Qseq, Y, F, F, F, F,
                                              (long)NF, (long)FF, (long)NF, 0, 0);
            // h1top[t] = relu(A[t][:256,:] @ Y[t]), t=0..6, split-K x4
            gemm_big<<<dim3(4, 2, 28), 256>>>(Aadj, Y, part, 1024, NN, F, F,
                                              (long)NN * NN, (long)NF, (long)FF, 0, 2);
            reduce_relu<<<7 * FF / 256, 256>>>(part, h1top);
            // h1full = relu(A[7] @ Y[7])
            gemm_big<<<dim3(4, 32, 1), 256>>>(Aadj + 7L * NN * NN, Y + 7L * NF, h1full,
                                              NN, NN, F, F, 0, 0, 0, 1, 0);
            copy1<<<FF / 256, 256>>>(h1full, h1top + 7L * FF);
        }
    }

    // out = relu(A[7] @ (h1full @ Q1_final))
    gemm_big<<<dim3(4, 32, 1), 256>>>(h1full, Q, Z, F, F, F, F, 0, 0, 0, 0, 0);
    gemm_big<<<dim3(4, 32, 1), 256>>>(Aadj + 7L * NN * NN, Z, (float*)d_out,
                                      NN, NN, F, F, 0, 0, 0, 1, 0);
}

// round 4
// speedup vs baseline: 1.6166x; 1.1027x over previous
#include <cuda_runtime.h>
#include <math.h>

typedef unsigned long long ull;

#define T 8
#define NN 4096
#define F 256
#define FF (F*F)          // 65536
#define NF (NN*F)         // 1048576
#define NSPLIT 8
#define GRU_GRID 128

// ---------------- scratch (static device memory; no allocations) -----------
__device__ float g_zt[T*FF];
__device__ float g_P[3*T*FF];       // [gate][t][FF]
__device__ float g_Q[FF];
__device__ float g_Qseq[T*FF];
__device__ float g_W3[3*FF];        // packed Wz,Wr,Wh
__device__ float g_upd[FF];
__device__ float g_RQ[FF];
__device__ float g_th[T*F];
__device__ float g_Y[T*NF];
__device__ float g_part[7*NSPLIT*FF];
__device__ float g_h1top[T*FF];
__device__ float g_h1full[NF];
__device__ float g_Z[NF];
__device__ unsigned g_bar[64];

// ---------------- f32x2 helpers --------------------------------------------
__device__ __forceinline__ ull pk2(float lo, float hi) {
    ull r; asm("mov.b64 %0, {%1, %2};" : "=l"(r) : "f"(lo), "f"(hi)); return r;
}
__device__ __forceinline__ float lo32(ull v){ return __uint_as_float((unsigned)v); }
__device__ __forceinline__ float hi32(ull v){ return __uint_as_float((unsigned)(v >> 32)); }
#define FMA2(acc, a, b) asm("fma.rn.f32x2 %0, %1, %2, %0;" : "+l"(acc) : "l"(a), "l"(b))

// ---------------- big GEMM: 128x64 tile, FFMA2, double-buffered -------------
// mode 0: A+=z*sA, B+=z*sB, C+=z*sC
// mode 1: A+=(z>>3)*sA, B+=(z&7)*sB, C+=z*sC          (P = W[g] @ zt[t])
// mode 2: t=z>>3,s=z&7: A+=t*sA + s*K, B+=t*sB + s*K*ldb, C+=z*sC (split-K x8)
__global__ void __launch_bounds__(256, 2) gemm_big(
    const float* __restrict__ Ab, const float* __restrict__ Bb, float* __restrict__ Cb,
    int K, int lda, int ldb, int ldc,
    long sA, long sB, long sC, int act, int mode)
{
    const int z = blockIdx.z;
    const float* A; const float* B; float* C;
    if (mode == 0)      { A = Ab + z * sA; B = Bb + z * sB; C = Cb + z * sC; }
    else if (mode == 1) { A = Ab + (long)(z >> 3) * sA; B = Bb + (long)(z & 7) * sB; C = Cb + (long)z * sC; }
    else                { int t = z >> 3, s = z & 7;
                          A = Ab + (long)t * sA + (long)s * K;
                          B = Bb + (long)t * sB + (long)s * K * ldb;
                          C = Cb + (long)z * sC; }

    __shared__ float As[2][16][136];
    __shared__ float Bs[2][16][64];

    const int tid = threadIdx.x;
    const int tx = tid & 15, ty = tid >> 4;
    const long bm = (long)blockIdx.y << 7;
    const int  bn = blockIdx.x << 6;

    const int a_row = tid >> 2;
    const int a_kc  = (tid & 3) << 2;
    const int b_kr  = tid >> 4;
    const int b_kc  = (tid & 15) << 2;

    const float* Ap0 = A + (bm + a_row) * (long)lda + a_kc;
    const float* Ap1 = Ap0 + (long)64 * lda;
    const float* Bp  = B + (long)b_kr * ldb + bn + b_kc;

    {
        float4 va0 = *(const float4*)Ap0;
        float4 va1 = *(const float4*)Ap1;
        float4 vb  = *(const float4*)Bp;
        As[0][a_kc+0][a_row] = va0.x; As[0][a_kc+1][a_row] = va0.y;
        As[0][a_kc+2][a_row] = va0.z; As[0][a_kc+3][a_row] = va0.w;
        As[0][a_kc+0][a_row+64] = va1.x; As[0][a_kc+1][a_row+64] = va1.y;
        As[0][a_kc+2][a_row+64] = va1.z; As[0][a_kc+3][a_row+64] = va1.w;
        *(float4*)&Bs[0][b_kr][b_kc] = vb;
    }
    __syncthreads();

    ull acc[4][4];
#pragma unroll
    for (int p = 0; p < 4; p++)
#pragma unroll
        for (int j = 0; j < 4; j++) acc[p][j] = 0ULL;

    const int nIter = K >> 4;
    int buf = 0;
    for (int it = 0; it < nIter; ++it) {
        float4 na0, na1, nb;
        const bool more = (it + 1 < nIter);
        if (more) {
            na0 = *(const float4*)(Ap0 + (it + 1) * 16);
            na1 = *(const float4*)(Ap1 + (it + 1) * 16);
            nb  = *(const float4*)(Bp + (long)(it + 1) * 16 * ldb);
        }
#pragma unroll
        for (int k = 0; k < 16; ++k) {
            ull a0 = *(const ull*)&As[buf][k][(ty<<3) + 0];
            ull a1 = *(const ull*)&As[buf][k][(ty<<3) + 2];
            ull a2 = *(const ull*)&As[buf][k][(ty<<3) + 4];
            ull a3 = *(const ull*)&As[buf][k][(ty<<3) + 6];
            float4 bv = *(const float4*)&Bs[buf][k][tx<<2];
            ull b0 = pk2(bv.x, bv.x), b1 = pk2(bv.y, bv.y);
            ull b2 = pk2(bv.z, bv.z), b3 = pk2(bv.w, bv.w);
            FMA2(acc[0][0], a0, b0); FMA2(acc[0][1], a0, b1); FMA2(acc[0][2], a0, b2); FMA2(acc[0][3], a0, b3);
            FMA2(acc[1][0], a1, b0); FMA2(acc[1][1], a1, b1); FMA2(acc[1][2], a1, b2); FMA2(acc[1][3], a1, b3);
            FMA2(acc[2][0], a2, b0); FMA2(acc[2][1], a2, b1); FMA2(acc[2][2], a2, b2); FMA2(acc[2][3], a2, b3);
            FMA2(acc[3][0], a3, b0); FMA2(acc[3][1], a3, b1); FMA2(acc[3][2], a3, b2); FMA2(acc[3][3], a3, b3);
        }
        if (more) {
            const int nbuf = buf ^ 1;
            As[nbuf][a_kc+0][a_row] = na0.x; As[nbuf][a_kc+1][a_row] = na0.y;
            As[nbuf][a_kc+2][a_row] = na0.z; As[nbuf][a_kc+3][a_row] = na0.w;
            As[nbuf][a_kc+0][a_row+64] = na1.x; As[nbuf][a_kc+1][a_row+64] = na1.y;
            As[nbuf][a_kc+2][a_row+64] = na1.z; As[nbuf][a_kc+3][a_row+64] = na1.w;
            *(float4*)&Bs[nbuf][b_kr][b_kc] = nb;
        }
        __syncthreads();
        buf ^= 1;
    }

#pragma unroll
    for (int p = 0; p < 4; ++p) {
        float4 vlo = make_float4(lo32(acc[p][0]), lo32(acc[p][1]), lo32(acc[p][2]), lo32(acc[p][3]));
        float4 vhi = make_float4(hi32(acc[p][0]), hi32(acc[p][1]), hi32(acc[p][2]), hi32(acc[p][3]));
        if (act) {
            vlo.x = fmaxf(vlo.x, 0.f); vlo.y = fmaxf(vlo.y, 0.f);
            vlo.z = fmaxf(vlo.z, 0.f); vlo.w = fmaxf(vlo.w, 0.f);
            vhi.x = fmaxf(vhi.x, 0.f); vhi.y = fmaxf(vhi.y, 0.f);
            vhi.z = fmaxf(vhi.z, 0.f); vhi.w = fmaxf(vhi.w, 0.f);
        }
        long r = bm + (ty << 3) + (p << 1);
        *(float4*)&C[r * (long)ldc + bn + (tx << 2)]       = vlo;
        *(float4*)&C[(r + 1) * (long)ldc + bn + (tx << 2)] = vhi;
    }
}

// ---------------- persistent GRU chain --------------------------------------
__device__ __forceinline__ void grid_bar(unsigned* ctr, unsigned nblk) {
    __syncthreads();
    if (threadIdx.x == 0) {
        __threadfence();
        unsigned prev = atomicAdd(ctr, 1u);
        if (prev + 1u < nblk) {
            while (*(volatile unsigned*)ctr < nblk) { }
        }
        __threadfence();
    }
    __syncthreads();
}

// 32x32 tile of (A[32,256] @ B[:,32]) with A rows at gA (stride F),
// B cols at gB (stride F). acc: M-packed pairs, 2 cols per thread.
__device__ __forceinline__ void tile32(
    const float* __restrict__ gA, const float* __restrict__ gB,
    float (*As)[16][36], float (*Bs)[16][36], ull* acc)
{
    const int tid = threadIdx.x;
    const int ty = tid >> 4, tx = tid & 15;
    acc[0] = 0ULL; acc[1] = 0ULL;

    const int la_r = tid >> 2;          // tid<128: 0..31
    const int la_k = (tid & 3) << 2;
    const int lb_u = tid & 127;
    const int lb_k = lb_u >> 3;         // 0..15
    const int lb_n = (lb_u & 7) << 2;   // 0..28

    {
        float4 v;
        if (tid < 128) {
            v = *(const float4*)(gA + la_r * F + la_k);
            As[0][la_k+0][la_r] = v.x; As[0][la_k+1][la_r] = v.y;
            As[0][la_k+2][la_r] = v.z; As[0][la_k+3][la_r] = v.w;
        } else {
            v = *(const float4*)(gB + lb_k * F + lb_n);
            *(float4*)&Bs[0][lb_k][lb_n] = v;
        }
    }
    __syncthreads();

    int buf = 0;
    for (int it = 0; it < 16; ++it) {
        float4 nv;
        const bool more = (it < 15);
        if (more) {
            int k0 = (it + 1) << 4;
            if (tid < 128) nv = *(const float4*)(gA + la_r * F + k0 + la_k);
            else           nv = *(const float4*)(gB + (k0 + lb_k) * F + lb_n);
        }
#pragma unroll
        for (int k = 0; k < 16; ++k) {
            ull av = *(const ull*)&As[buf][k][ty << 1];
            ull bv = *(const ull*)&Bs[buf][k][tx << 1];
            float b0 = lo32(bv), b1 = hi32(bv);
            ull bb0 = pk2(b0, b0);
            ull bb1 = pk2(b1, b1);
            FMA2(acc[0], av, bb0);
            FMA2(acc[1], av, bb1);
        }
        if (more) {
            const int nb = buf ^ 1;
            if (tid < 128) {
                As[nb][la_k+0][la_r] = nv.x; As[nb][la_k+1][la_r] = nv.y;
                As[nb][la_k+2][la_r] = nv.z; As[nb][la_k+3][la_r] = nv.w;
            } else {
                *(float4*)&Bs[nb][lb_k][lb_n] = nv;
            }
        }
        __syncthreads();
        buf ^= 1;
    }
}

__device__ __forceinline__ float sigf(float x) { return 1.0f / (1.0f + expf(-x)); }

__global__ void __launch_bounds__(256, 1) gru_chain(
    const float* __restrict__ Uz, const float* __restrict__ Ur, const float* __restrict__ Uh,
    const float* __restrict__ P,
    const float* __restrict__ bz, const float* __restrict__ br, const float* __restrict__ bh,
    const float* __restrict__ Q0, float* __restrict__ Q,
    float* __restrict__ upd, float* __restrict__ RQ,
    float* __restrict__ Qseq, unsigned* __restrict__ bar)
{
    __shared__ float As[2][16][36];
    __shared__ float Bs[2][16][36];

    const int tid = threadIdx.x;
    const int bid = blockIdx.x;
    const int gate = bid >> 6;          // phase A: 0=z (blocks 0-63), 1=r (64-127)
    const int id   = bid & 63;
    const int tm   = id >> 3;           // 0..7  (row tile)
    const int tn   = id & 7;            // 0..7  (col tile)
    const int ty = tid >> 4, tx = tid & 15;
    const int rb = tm * 32 + (ty << 1);
    const int cb = tn * 32 + (tx << 1);

    for (int t = 0; t < T; ++t) {
        const float* Qprev = (t == 0) ? Q0 : Q;

        // ---- phase A: z and r gates (all 128 blocks) ----
        {
            const float* Amat = gate ? Ur : Uz;
            const float* Pg   = P + (long)((gate ? T : 0) + t) * FF;
            const float* bb   = gate ? br : bz;
            ull acc[2];
            tile32(Amat + (long)tm * 32 * F, Qprev + tn * 32, As, Bs, acc);
#pragma unroll
            for (int j = 0; j < 2; ++j) {
#pragma unroll
                for (int e = 0; e < 2; ++e) {
                    long idx = (long)(rb + e) * F + cb + j;
                    float a = e ? hi32(acc[j]) : lo32(acc[j]);
                    float s = sigf(a + Pg[idx] + bb[idx]);
                    if (!gate) upd[idx] = s;
                    else       RQ[idx] = s * Qprev[idx];
                }
            }
        }
        grid_bar(bar + 2 * t, GRU_GRID);

        // ---- phase B: h gate + Q update (blocks 0-63) ----
        if (bid < 64) {
            const float* Ph = P + (long)(2 * T + t) * FF;
            ull acc[2];
            tile32(Uh + (long)tm * 32 * F, RQ + tn * 32, As, Bs, acc);
#pragma unroll
            for (int j = 0; j < 2; ++j) {
#pragma unroll
                for (int e = 0; e < 2; ++e) {
                    long idx = (long)(rb + e) * F + cb + j;
                    float a = e ? hi32(acc[j]) : lo32(acc[j]);
                    float h = tanhf(a + Ph[idx] + bh[idx]);
                    float u = upd[idx];
                    float q = (1.0f - u) * Qprev[idx] + u * h;
                    Q[idx] = q;
                    if (Qseq) Qseq[(long)t * FF + idx] = q;
                }
            }
        }
        grid_bar(bar + 2 * t + 1, GRU_GRID);
    }
}

// ---------------- scores + transposed zt ------------------------------------
__global__ void score_kernel(const float* __restrict__ embs, long stride, int ld,
                             const float* __restrict__ scorer, float* __restrict__ th)
{
    const int t = blockIdx.x;
    const float* E = embs + (long)t * stride;
    __shared__ float sc[F];
    __shared__ float red[256];
    const int tid = threadIdx.x;
    float s = scorer[tid];
    sc[tid] = s;
    red[tid] = s * s;
    __syncthreads();
    for (int off = 128; off > 0; off >>= 1) {
        if (tid < off) red[tid] += red[tid + off];
        __syncthreads();
    }
    const float inv_sn = 1.0f / sqrtf(red[0]);
    float dot = 0.f;
    const float* row = E + (long)tid * ld;
#pragma unroll 8
    for (int c = 0; c < F; c++) dot += row[c] * sc[c];
    th[t * F + tid] = tanhf(dot * inv_sn);
}

// zt[t][c*256+r] = E[r][c] * th[r]  — smem-tiled transpose
__global__ void zt_trans(const float* __restrict__ embs, long stride, int ld,
                         const float* __restrict__ th, float* __restrict__ zt)
{
    const int t = blockIdx.y;
    const int tile = blockIdx.x;
    const int ti = tile >> 3, tj = tile & 7;   // ti: E row block, tj: E col block
    const float* E = embs + (long)t * stride;
    float* Z = zt + (long)t * FF;

    __shared__ float tb[32][33];
    const int tx = threadIdx.x & 31;
    const int ty8 = threadIdx.x >> 5;          // 0..7

#pragma unroll
    for (int r0 = 0; r0 < 4; ++r0) {
        int r = ty8 + (r0 << 3);
        tb[r][tx] = E[(long)(ti * 32 + r) * ld + tj * 32 + tx] * th[t * F + ti * 32 + r];
    }
    __syncthreads();
#pragma unroll
    for (int c0 = 0; c0 < 4; ++c0) {
        int c = ty8 + (c0 << 3);
        Z[(long)(tj * 32 + c) * F + ti * 32 + tx] = tb[tx][c];
    }
}

// ---------------- misc -------------------------------------------------------
__global__ void reduce_relu(const float* __restrict__ part, float* __restrict__ out)
{
    long i = (long)blockIdx.x * 256 + threadIdx.x;   // over 7*FF
    long t = i >> 16;
    long r = i & (FF - 1);
    const float* p = part + t * (long)(NSPLIT * FF) + r;
    float s = 0.f;
#pragma unroll
    for (int j = 0; j < NSPLIT; ++j) s += p[(long)j * FF];
    out[i] = fmaxf(s, 0.0f);
}

__global__ void pack3(const float* __restrict__ a, const float* __restrict__ b,
                      const float* __restrict__ c, float* __restrict__ dst)
{
    int i = blockIdx.x * 256 + threadIdx.x;
    dst[i] = a[i]; dst[FF + i] = b[i]; dst[2 * FF + i] = c[i];
}

__global__ void copy1(const float* __restrict__ src, float* __restrict__ dst)
{
    int i = blockIdx.x * 256 + threadIdx.x;
    dst[i] = src[i];
}

__global__ void zero_bar(unsigned* b) { b[threadIdx.x] = 0u; }

// ---------------------------------------------------------------------------
extern "C" void kernel_launch(void* const* d_in, const int* in_sizes, int n_in,
                              void* d_out, int out_size)
{
    const float* Aadj = (const float*)d_in[0];  // [T,N,N]
    const float* X    = (const float*)d_in[1];  // [T,N,F]
    auto LP = [&](int l, int idx) { return (const float*)d_in[3 + l * 11 + idx]; };

    float *zt, *P, *Q, *Qseq, *W3, *upd, *RQ, *th, *Y, *part, *h1top, *h1full, *Z;
    unsigned* bar;
    cudaGetSymbolAddress((void**)&zt,     g_zt);
    cudaGetSymbolAddress((void**)&P,      g_P);
    cudaGetSymbolAddress((void**)&Q,      g_Q);
    cudaGetSymbolAddress((void**)&Qseq,   g_Qseq);
    cudaGetSymbolAddress((void**)&W3,     g_W3);
    cudaGetSymbolAddress((void**)&upd,    g_upd);
    cudaGetSymbolAddress((void**)&RQ,     g_RQ);
    cudaGetSymbolAddress((void**)&th,     g_th);
    cudaGetSymbolAddress((void**)&Y,      g_Y);
    cudaGetSymbolAddress((void**)&part,   g_part);
    cudaGetSymbolAddress((void**)&h1top,  g_h1top);
    cudaGetSymbolAddress((void**)&h1full, g_h1full);
    cudaGetSymbolAddress((void**)&Z,      g_Z);
    cudaGetSymbolAddress((void**)&bar,    g_bar);

    zero_bar<<<1, 64>>>(bar);

    for (int l = 0; l < 2; ++l) {
        const float* embs = (l == 0) ? X : h1top;
        long estride = (l == 0) ? (long)NF : (long)FF;

        score_kernel<<<T, 256>>>(embs, estride, F, LP(l, 0), th);
        zt_trans<<<dim3(64, T), 256>>>(embs, estride, F, th, zt);

        pack3<<<FF / 256, 256>>>(LP(l, 1), LP(l, 4), LP(l, 7), W3);
        gemm_big<<<dim3(4, 2, 24), 256>>>(W3, zt, P, F, F, F, F,
                                          (long)FF, (long)FF, (long)FF, 0, 1);

        gru_chain<<<GRU_GRID, 256>>>(LP(l, 2), LP(l, 5), LP(l, 8), P,
                                     LP(l, 3), LP(l, 6), LP(l, 9),
                                     LP(l, 10), Q, upd, RQ,
                                     (l == 0) ? Qseq : nullptr,
                                     bar + l * 32);

        if (l == 0) {
            // Y[t] = X[t] @ Qseq[t]
            gemm_big<<<dim3(4, 32, 8), 256>>>(X, Qseq, Y, F, F, F, F,
                                              (long)NF, (long)FF, (long)NF, 0, 0);
            // h1top[t] = relu(A[t][:256,:] @ Y[t]), t=0..6, split-K x8
            gemm_big<<<dim3(4, 2, 56), 256>>>(Aadj, Y, part, NN / NSPLIT, NN, F, F,
                                              (long)NN * NN, (long)NF, (long)FF, 0, 2);
            reduce_relu<<<7 * FF / 256, 256>>>(part, h1top);
            // h1full = relu(A[7] @ Y[7])
            gemm_big<<<dim3(4, 32, 1), 256>>>(Aadj + 7L * NN * NN, Y + 7L * NF, h1full,
                                              NN, NN, F, F, 0, 0, 0, 1, 0);
            copy1<<<FF / 256, 256>>>(h1full, h1top + 7L * FF);
        }
    }

    // out = relu(A[7] @ (h1full @ Q1_final))
    gemm_big<<<dim3(4, 32, 1), 256>>>(h1full, Q, Z, F, F, F, F, 0, 0, 0, 0, 0);
    gemm_big<<<dim3(4, 32, 1), 256>>>(Aadj + 7L * NN * NN, Z, (float*)d_out,
                                      NN, NN, F, F, 0, 0, 0, 1, 0);
}